// round 15
// baseline (speedup 1.0000x reference)
#include <cuda_runtime.h>
#include <cuda_fp16.h>

#define BATCH 16
#define LQ    1024
#define LKV   1024
#define DIM   512

typedef unsigned int u32;

// ---------------------------------------------------------------------------
// Static device scratch (allocation-free rule; __device__ globals allowed)
// ---------------------------------------------------------------------------
__device__ __align__(16) __half g_QH [(size_t)BATCH * LQ  * DIM];
__device__ __align__(16) __half g_QL [(size_t)BATCH * LQ  * DIM];
__device__ __align__(16) __half g_VH [(size_t)BATCH * LKV * DIM];
__device__ __align__(16) __half g_VL [(size_t)BATCH * LKV * DIM];
__device__ __align__(16) __half g_VTH[(size_t)BATCH * DIM * LKV];  // V^T [b, d, kv]
__device__ __align__(16) __half g_VTL[(size_t)BATCH * DIM * LKV];
__device__ __align__(16) __half g_PH [(size_t)BATCH * LQ  * LKV];
__device__ __align__(16) __half g_PL [(size_t)BATCH * LQ  * LKV];

// ---------------------------------------------------------------------------
// Helpers
// ---------------------------------------------------------------------------
__device__ __forceinline__ u32 smem_u32(const void* p) {
    u32 a;
    asm("{ .reg .u64 t; cvta.to.shared.u64 t, %1; cvt.u32.u64 %0, t; }"
        : "=r"(a) : "l"(p));
    return a;
}

__device__ __forceinline__ void cp16(u32 dst, const void* src) {
    asm volatile("cp.async.cg.shared.global [%0], [%1], 16;" :: "r"(dst), "l"(src));
}
#define CP_COMMIT() asm volatile("cp.async.commit_group;" ::: "memory")

#define LDSM4(r, a) \
    asm volatile("ldmatrix.sync.aligned.m8n8.x4.shared.b16 {%0,%1,%2,%3}, [%4];" \
        : "=r"((r)[0]), "=r"((r)[1]), "=r"((r)[2]), "=r"((r)[3]) : "r"(a))

#define MMA16816(d, a, b0, b1) \
    asm volatile("mma.sync.aligned.m16n8k16.row.col.f32.f16.f16.f32 " \
        "{%0,%1,%2,%3}, {%4,%5,%6,%7}, {%8,%9}, {%0,%1,%2,%3};" \
        : "+f"((d)[0]), "+f"((d)[1]), "+f"((d)[2]), "+f"((d)[3]) \
        : "r"((a)[0]), "r"((a)[1]), "r"((a)[2]), "r"((a)[3]), "r"(b0), "r"(b1))

__device__ __forceinline__ void split2h(float x, __half& h, __half& l) {
    h = __float2half(x);
    l = __float2half(x - __half2float(h));
}

__device__ __forceinline__ u32 packh2(__half a, __half b) {
    __half2 t = __halves2half2(a, b);
    return *(u32*)&t;
}

// ---------------------------------------------------------------------------
// fp32 -> (hi, lo) fp16 split, 4 elems/thread
// ---------------------------------------------------------------------------
__global__ void cvt_split_kernel(const float* __restrict__ x,
                                 __half* __restrict__ H, __half* __restrict__ L)
{
    size_t i = ((size_t)blockIdx.x * blockDim.x + threadIdx.x) * 4;
    float4 v = *(const float4*)(x + i);
    __half h0, h1, h2, h3, l0, l1, l2, l3;
    split2h(v.x, h0, l0); split2h(v.y, h1, l1);
    split2h(v.z, h2, l2); split2h(v.w, h3, l3);
    *(uint2*)(H + i) = make_uint2(packh2(h0, h1), packh2(h2, h3));
    *(uint2*)(L + i) = make_uint2(packh2(l0, l1), packh2(l2, l3));
}

// ---------------------------------------------------------------------------
// V: linear split + 32x32 tiled transpose split. grid (DIM/32, LKV/32, B),
// block (32,8).
// ---------------------------------------------------------------------------
__global__ void vtrans_kernel(const float* __restrict__ V,
                              __half* __restrict__ VH, __half* __restrict__ VL,
                              __half* __restrict__ VTH, __half* __restrict__ VTL)
{
    __shared__ float sm[32][33];
    int tx = threadIdx.x, ty = threadIdx.y;
    int d0 = blockIdx.x * 32, k0 = blockIdx.y * 32, b = blockIdx.z;
    const float* src = V + (size_t)b * LKV * DIM;
    size_t lbase = (size_t)b * LKV * DIM;

#pragma unroll
    for (int j = 0; j < 4; j++) {
        int kk = k0 + ty + j * 8;
        float v = src[(size_t)kk * DIM + d0 + tx];
        sm[ty + j * 8][tx] = v;
        __half h, l; split2h(v, h, l);
        size_t o = lbase + (size_t)kk * DIM + d0 + tx;
        VH[o] = h; VL[o] = l;
    }
    __syncthreads();
    size_t tbase = (size_t)b * DIM * LKV;
#pragma unroll
    for (int j = 0; j < 4; j++) {
        int dd = d0 + ty + j * 8;
        float v = sm[tx][ty + j * 8];
        __half h, l; split2h(v, h, l);
        size_t o = tbase + (size_t)dd * LKV + k0 + tx;
        VTH[o] = h; VTL[o] = l;
    }
}

// ---------------------------------------------------------------------------
// Softmax over 1024 cols in place + split P into fp16 hi/lo (packed stores).
// ---------------------------------------------------------------------------
__global__ void softmax_split_kernel(float* __restrict__ S,
                                     __half* __restrict__ PH, __half* __restrict__ PL)
{
    __shared__ float red[16];
    size_t row = blockIdx.x;
    float4* p = (float4*)(S + row * 1024);
    const int tid = threadIdx.x, lane = tid & 31, w = tid >> 5;

    float4 x = p[tid];

    float m = fmaxf(fmaxf(x.x, x.y), fmaxf(x.z, x.w));
#pragma unroll
    for (int o = 16; o; o >>= 1) m = fmaxf(m, __shfl_xor_sync(0xFFFFFFFFu, m, o));
    if (lane == 0) red[w] = m;
    __syncthreads();
    float bm = red[0];
#pragma unroll
    for (int i = 1; i < 8; i++) bm = fmaxf(bm, red[i]);

    float4 e;
    e.x = __expf(x.x - bm); e.y = __expf(x.y - bm);
    e.z = __expf(x.z - bm); e.w = __expf(x.w - bm);

    float s = (e.x + e.y) + (e.z + e.w);
#pragma unroll
    for (int o = 16; o; o >>= 1) s += __shfl_xor_sync(0xFFFFFFFFu, s, o);
    __syncthreads();
    if (lane == 0) red[8 + w] = s;
    __syncthreads();
    float bs = red[8];
#pragma unroll
    for (int i = 1; i < 8; i++) bs += red[8 + i];

    float inv = 1.0f / bs;
    e.x *= inv; e.y *= inv; e.z *= inv; e.w *= inv;
    p[tid] = e;

    size_t o = row * 1024 + (size_t)tid * 4;
    __half h0, h1, h2, h3, l0, l1, l2, l3;
    split2h(e.x, h0, l0); split2h(e.y, h1, l1);
    split2h(e.z, h2, l2); split2h(e.w, h3, l3);
    *(uint2*)(PH + o) = make_uint2(packh2(h0, h1), packh2(h2, h3));
    *(uint2*)(PL + o) = make_uint2(packh2(l0, l1), packh2(l2, l3));
}

// ---------------------------------------------------------------------------
// HMMA GEMM NT with fp16 hi/lo split, templated on number of product terms:
//   NTERMS==3: C = AhBh + AhBl + AlBh   (GEMM1: scores need abs accuracy)
//   NTERMS==2: C = AhBh + AlBh          (GEMM2: B_lo term negligible)
// Tile 128x128, BK=32 halfs. 8 warps (2x4), warp tile 64x32.
// Smem rows padded to 80B (20r+4c mod 32 is a permutation -> conflict-free
// ldmatrix, 16B-aligned for cp.async).
// 2-stage cp.async pipeline + 2 CTAs/SM (occupancy was the R14 bottleneck:
// 1 CTA/SM -> 2 warps/SMSP couldn't hide HMMA+LDS latency; effective HMMA
// interval was ~14 cyc/SMSP).
// grid (N/128, M/128, BATCH), block 256.
// ---------------------------------------------------------------------------
#define KC      32
#define STAGES  2
#define ROWB    80
#define TILE_H  (128 * ROWB)          // 10240 B per operand tile
#define STAGE_B (4 * TILE_H)          // Ah, Al, Bh, Bl slots
#define SMEM_GEMM (STAGES * STAGE_B)  // 81920 B -> 2 CTAs/SM (163840 < 227KB)

template<int NTERMS>
__global__ void __launch_bounds__(256, 2)
gemm_nt_hmma(const __half* __restrict__ Ah, const __half* __restrict__ Al,
             const __half* __restrict__ Bh, const __half* __restrict__ Bl,
             float* __restrict__ C, int K, long sA, long sB, long sC)
{
    extern __shared__ char smem[];
    const u32 sb = smem_u32(smem);
    const int tid = threadIdx.x, wid = tid >> 5, lane = tid & 31;
    const int m0 = blockIdx.y * 128, n0 = blockIdx.x * 128, bz = blockIdx.z;
    const int Ncols = gridDim.x * 128;
    const int wm = wid >> 2, wn = wid & 3;

    // fill mapping: 64 threads per operand tile, 8 x 16B chunks each
    const int t4 = tid >> 6, lg = tid & 63;
    const long aoff = (long)bz * sA + (long)m0 * K;
    const long boff = (long)bz * sB + (long)n0 * K;
    const __half* tsrc =
        (t4 == 0) ? (Ah + aoff) : (t4 == 1) ? (Al + aoff) :
        (t4 == 2) ? (Bh + boff) : (Bl + boff);
    const bool do_fill = (NTERMS == 3) || (t4 != 3);   // skip Bl tile for 2-term
    const int nT = K / KC;

    auto fill = [&](int kc) {
        if (do_fill) {
            u32 dbase = sb + (u32)(kc % STAGES) * STAGE_B + (u32)t4 * TILE_H;
            const __half* ksrc = tsrc + (long)kc * KC;
#pragma unroll
            for (int i = 0; i < 8; i++) {
                int idx = lg + i * 64;
                int row = idx >> 2, c = idx & 3;
                cp16(dbase + (u32)(row * ROWB + c * 16), ksrc + (long)row * K + c * 8);
            }
        }
        CP_COMMIT();
    };

#pragma unroll
    for (int s = 0; s < STAGES; s++) fill(s);

    float acc[4][4][4];
#pragma unroll
    for (int mi = 0; mi < 4; mi++)
#pragma unroll
        for (int nt = 0; nt < 4; nt++)
#pragma unroll
            for (int j = 0; j < 4; j++) acc[mi][nt][j] = 0.0f;

    // ldmatrix per-thread base offsets (bytes within an operand tile)
    const u32 aoffs = (u32)((wm * 64 + (lane & 15)) * ROWB + (lane >> 4) * 16);
    const u32 boffs = (u32)((wn * 32 + ((lane >> 4) << 3) + (lane & 7)) * ROWB
                            + ((lane >> 3) & 1) * 16);

    for (int t = 0; t < nT; t++) {
        // 2-stage: at most 1 fill (chunk t+1) may remain outstanding
        if (t + 1 < nT) asm volatile("cp.async.wait_group 1;" ::: "memory");
        else            asm volatile("cp.async.wait_group 0;" ::: "memory");
        __syncthreads();

        const u32 st = sb + (u32)(t % STAGES) * STAGE_B;
#pragma unroll
        for (int kk = 0; kk < 2; kk++) {
            u32 ahf[4][4], alf[4][4], bf[2][4];
#pragma unroll
            for (int mi = 0; mi < 4; mi++) {
                LDSM4(ahf[mi], st + aoffs + (u32)(mi * 16 * ROWB + kk * 32));
                LDSM4(alf[mi], st + TILE_H + aoffs + (u32)(mi * 16 * ROWB + kk * 32));
            }
#pragma unroll
            for (int p = 0; p < 2; p++)
                LDSM4(bf[p], st + 2 * TILE_H + boffs + (u32)(p * 16 * ROWB + kk * 32));

            // terms using Bh: Ah*Bh and Al*Bh
#pragma unroll
            for (int mi = 0; mi < 4; mi++)
#pragma unroll
                for (int nt = 0; nt < 4; nt++) {
                    u32 b0 = bf[nt >> 1][(nt & 1) * 2], b1 = bf[nt >> 1][(nt & 1) * 2 + 1];
                    MMA16816(acc[mi][nt], ahf[mi], b0, b1);
                    MMA16816(acc[mi][nt], alf[mi], b0, b1);
                }

            if (NTERMS == 3) {
                // reload bf with Bl (frees register pressure vs keeping both live)
#pragma unroll
                for (int p = 0; p < 2; p++)
                    LDSM4(bf[p], st + 3 * TILE_H + boffs + (u32)(p * 16 * ROWB + kk * 32));
#pragma unroll
                for (int mi = 0; mi < 4; mi++)
#pragma unroll
                    for (int nt = 0; nt < 4; nt++) {
                        u32 b0 = bf[nt >> 1][(nt & 1) * 2], b1 = bf[nt >> 1][(nt & 1) * 2 + 1];
                        MMA16816(acc[mi][nt], ahf[mi], b0, b1);
                    }
            }
        }
        __syncthreads();
        if (t + STAGES < nT) fill(t + STAGES);
    }

    // epilogue: fp32 acc frags straight to gmem
    float* Cb = C + (long)bz * sC;
    const int r = lane >> 2, c2 = (lane & 3) * 2;
#pragma unroll
    for (int mi = 0; mi < 4; mi++)
#pragma unroll
        for (int nt = 0; nt < 4; nt++) {
            long row = m0 + wm * 64 + mi * 16 + r;
            long col = n0 + wn * 32 + nt * 8 + c2;
            *(float2*)&Cb[row * Ncols + col] =
                make_float2(acc[mi][nt][0], acc[mi][nt][1]);
            *(float2*)&Cb[(row + 8) * Ncols + col] =
                make_float2(acc[mi][nt][2], acc[mi][nt][3]);
        }
}

// ---------------------------------------------------------------------------
// Launch
// ---------------------------------------------------------------------------
extern "C" void kernel_launch(void* const* d_in, const int* in_sizes, int n_in,
                              void* d_out, int out_size)
{
    const float* Q = (const float*)d_in[0];
    const float* V = (const float*)d_in[1];
    float* out  = (float*)d_out;
    float* ctx  = out;                                   // [B, LQ, DIM]
    float* attn = out + (size_t)BATCH * LQ * DIM;        // [B, LQ, LKV]

    void *qh, *ql, *vh, *vl, *vth, *vtl, *ph, *pl;
    cudaGetSymbolAddress(&qh,  g_QH);  cudaGetSymbolAddress(&ql,  g_QL);
    cudaGetSymbolAddress(&vh,  g_VH);  cudaGetSymbolAddress(&vl,  g_VL);
    cudaGetSymbolAddress(&vth, g_VTH); cudaGetSymbolAddress(&vtl, g_VTL);
    cudaGetSymbolAddress(&ph,  g_PH);  cudaGetSymbolAddress(&pl,  g_PL);

    cudaFuncSetAttribute(gemm_nt_hmma<3>,
                         cudaFuncAttributeMaxDynamicSharedMemorySize, SMEM_GEMM);
    cudaFuncSetAttribute(gemm_nt_hmma<2>,
                         cudaFuncAttributeMaxDynamicSharedMemorySize, SMEM_GEMM);

    // 1) split Q
    {
        size_t n = (size_t)BATCH * LQ * DIM;
        cvt_split_kernel<<<(unsigned)(n / 4 / 256), 256>>>(
            Q, (__half*)qh, (__half*)ql);
    }
    // 2) split V + transposed split
    vtrans_kernel<<<dim3(DIM / 32, LKV / 32, BATCH), dim3(32, 8)>>>(
        V, (__half*)vh, (__half*)vl, (__half*)vth, (__half*)vtl);

    // 3) S = Q @ V^T  (fp32 scores into attn region) — full 3-term accuracy
    gemm_nt_hmma<3><<<dim3(LKV / 128, LQ / 128, BATCH), 256, SMEM_GEMM>>>(
        (const __half*)qh, (const __half*)ql,
        (const __half*)vh, (const __half*)vl,
        attn, DIM, (long)LQ * DIM, (long)LKV * DIM, (long)LQ * LKV);

    // 4) softmax in place + split P
    softmax_split_kernel<<<BATCH * LQ, 256>>>(attn, (__half*)ph, (__half*)pl);

    // 5) context = P @ (V^T)^T — 2-term (V_lo contribution ~2^-12, negligible)
    gemm_nt_hmma<2><<<dim3(DIM / 128, LQ / 128, BATCH), 256, SMEM_GEMM>>>(
        (const __half*)ph, (const __half*)pl,
        (const __half*)vth, (const __half*)vtl,
        ctx, LKV, (long)LQ * LKV, (long)DIM * LKV, (long)LQ * DIM);
}

// round 17
// speedup vs baseline: 1.5331x; 1.5331x over previous
#include <cuda_runtime.h>
#include <cuda_fp16.h>

#define BATCH 16
#define LQ    1024
#define LKV   1024
#define DIM   512

typedef unsigned int u32;

// ---------------------------------------------------------------------------
// Static device scratch (allocation-free rule; __device__ globals allowed)
// ---------------------------------------------------------------------------
__device__ __align__(16) __half g_QH [(size_t)BATCH * LQ  * DIM];
__device__ __align__(16) __half g_QL [(size_t)BATCH * LQ  * DIM];
__device__ __align__(16) __half g_VH [(size_t)BATCH * LKV * DIM];
__device__ __align__(16) __half g_VL [(size_t)BATCH * LKV * DIM];
__device__ __align__(16) __half g_VTH[(size_t)BATCH * DIM * LKV];  // V^T [b, d, kv]
__device__ __align__(16) __half g_PH [(size_t)BATCH * LQ  * LKV];

// ---------------------------------------------------------------------------
// Helpers
// ---------------------------------------------------------------------------
__device__ __forceinline__ u32 smem_u32(const void* p) {
    u32 a;
    asm("{ .reg .u64 t; cvta.to.shared.u64 t, %1; cvt.u32.u64 %0, t; }"
        : "=r"(a) : "l"(p));
    return a;
}

__device__ __forceinline__ void cp16(u32 dst, const void* src) {
    asm volatile("cp.async.cg.shared.global [%0], [%1], 16;" :: "r"(dst), "l"(src));
}
#define CP_COMMIT() asm volatile("cp.async.commit_group;" ::: "memory")

#define LDSM4(r, a) \
    asm volatile("ldmatrix.sync.aligned.m8n8.x4.shared.b16 {%0,%1,%2,%3}, [%4];" \
        : "=r"((r)[0]), "=r"((r)[1]), "=r"((r)[2]), "=r"((r)[3]) : "r"(a))

#define MMA16816(d, a, b0, b1) \
    asm volatile("mma.sync.aligned.m16n8k16.row.col.f32.f16.f16.f32 " \
        "{%0,%1,%2,%3}, {%4,%5,%6,%7}, {%8,%9}, {%0,%1,%2,%3};" \
        : "+f"((d)[0]), "+f"((d)[1]), "+f"((d)[2]), "+f"((d)[3]) \
        : "r"((a)[0]), "r"((a)[1]), "r"((a)[2]), "r"((a)[3]), "r"(b0), "r"(b1))

__device__ __forceinline__ void split2h(float x, __half& h, __half& l) {
    h = __float2half(x);
    l = __float2half(x - __half2float(h));
}

__device__ __forceinline__ u32 packh2(__half a, __half b) {
    __half2 t = __halves2half2(a, b);
    return *(u32*)&t;
}

// ---------------------------------------------------------------------------
// fp32 -> (hi, lo) fp16 split, 4 elems/thread
// ---------------------------------------------------------------------------
__global__ void cvt_split_kernel(const float* __restrict__ x,
                                 __half* __restrict__ H, __half* __restrict__ L)
{
    size_t i = ((size_t)blockIdx.x * blockDim.x + threadIdx.x) * 4;
    float4 v = *(const float4*)(x + i);
    __half h0, h1, h2, h3, l0, l1, l2, l3;
    split2h(v.x, h0, l0); split2h(v.y, h1, l1);
    split2h(v.z, h2, l2); split2h(v.w, h3, l3);
    *(uint2*)(H + i) = make_uint2(packh2(h0, h1), packh2(h2, h3));
    *(uint2*)(L + i) = make_uint2(packh2(l0, l1), packh2(l2, l3));
}

// ---------------------------------------------------------------------------
// V: linear split (hi+lo, for GEMM1) + 32x32 tiled transpose (hi only, for
// GEMM2's 1-term path). grid (DIM/32, LKV/32, B), block (32,8).
// ---------------------------------------------------------------------------
__global__ void vtrans_kernel(const float* __restrict__ V,
                              __half* __restrict__ VH, __half* __restrict__ VL,
                              __half* __restrict__ VTH)
{
    __shared__ float sm[32][33];
    int tx = threadIdx.x, ty = threadIdx.y;
    int d0 = blockIdx.x * 32, k0 = blockIdx.y * 32, b = blockIdx.z;
    const float* src = V + (size_t)b * LKV * DIM;
    size_t lbase = (size_t)b * LKV * DIM;

#pragma unroll
    for (int j = 0; j < 4; j++) {
        int kk = k0 + ty + j * 8;
        float v = src[(size_t)kk * DIM + d0 + tx];
        sm[ty + j * 8][tx] = v;
        __half h, l; split2h(v, h, l);
        size_t o = lbase + (size_t)kk * DIM + d0 + tx;
        VH[o] = h; VL[o] = l;
    }
    __syncthreads();
    size_t tbase = (size_t)b * DIM * LKV;
#pragma unroll
    for (int j = 0; j < 4; j++) {
        int dd = d0 + ty + j * 8;
        float v = sm[tx][ty + j * 8];
        size_t o = tbase + (size_t)dd * LKV + k0 + tx;
        VTH[o] = __float2half(v);
    }
}

// ---------------------------------------------------------------------------
// Softmax over 1024 cols in place + P -> fp16 (hi only; GEMM2 is 1-term).
// ---------------------------------------------------------------------------
__global__ void softmax_split_kernel(float* __restrict__ S,
                                     __half* __restrict__ PH)
{
    __shared__ float red[16];
    size_t row = blockIdx.x;
    float4* p = (float4*)(S + row * 1024);
    const int tid = threadIdx.x, lane = tid & 31, w = tid >> 5;

    float4 x = p[tid];

    float m = fmaxf(fmaxf(x.x, x.y), fmaxf(x.z, x.w));
#pragma unroll
    for (int o = 16; o; o >>= 1) m = fmaxf(m, __shfl_xor_sync(0xFFFFFFFFu, m, o));
    if (lane == 0) red[w] = m;
    __syncthreads();
    float bm = red[0];
#pragma unroll
    for (int i = 1; i < 8; i++) bm = fmaxf(bm, red[i]);

    float4 e;
    e.x = __expf(x.x - bm); e.y = __expf(x.y - bm);
    e.z = __expf(x.z - bm); e.w = __expf(x.w - bm);

    float s = (e.x + e.y) + (e.z + e.w);
#pragma unroll
    for (int o = 16; o; o >>= 1) s += __shfl_xor_sync(0xFFFFFFFFu, s, o);
    __syncthreads();
    if (lane == 0) red[8 + w] = s;
    __syncthreads();
    float bs = red[8];
#pragma unroll
    for (int i = 1; i < 8; i++) bs += red[8 + i];

    float inv = 1.0f / bs;
    e.x *= inv; e.y *= inv; e.z *= inv; e.w *= inv;
    p[tid] = e;

    size_t o = row * 1024 + (size_t)tid * 4;
    *(uint2*)(PH + o) = make_uint2(
        packh2(__float2half(e.x), __float2half(e.y)),
        packh2(__float2half(e.z), __float2half(e.w)));
}

// ---------------------------------------------------------------------------
// HMMA GEMM NT with fp16 hi/lo split, templated on number of product terms:
//   NTERMS==3: C = AhBh + AhBl + AlBh   (GEMM1: scores need abs accuracy)
//   NTERMS==1: C = AhBh                 (GEMM2: pure fp16; P/V lo negligible)
// Tile 128x128, BK=32 halfs. 8 warps (2x4), warp tile 64x32.
// Smem rows padded to 80B (20r+4c mod 32 is a permutation -> conflict-free
// ldmatrix, 16B-aligned for cp.async). 3-stage cp.async pipeline, 1 CTA/SM
// (R14 config: the best measured; R15 showed 2-stage + 2 CTA/SM regresses).
// grid (N/128, M/128, BATCH), block 256.
// ---------------------------------------------------------------------------
#define KC      32
#define STAGES  3
#define ROWB    80
#define TILE_H  (128 * ROWB)          // 10240 B per operand tile
#define STAGE_B (4 * TILE_H)          // Ah, Al, Bh, Bl slots
#define SMEM_GEMM (STAGES * STAGE_B)  // 122880 B

template<int NTERMS>
__global__ void __launch_bounds__(256, 1)
gemm_nt_hmma(const __half* __restrict__ Ah, const __half* __restrict__ Al,
             const __half* __restrict__ Bh, const __half* __restrict__ Bl,
             float* __restrict__ C, int K, long sA, long sB, long sC)
{
    extern __shared__ char smem[];
    const u32 sb = smem_u32(smem);
    const int tid = threadIdx.x, wid = tid >> 5, lane = tid & 31;
    const int m0 = blockIdx.y * 128, n0 = blockIdx.x * 128, bz = blockIdx.z;
    const int Ncols = gridDim.x * 128;
    const int wm = wid >> 2, wn = wid & 3;

    // fill mapping: 64 threads per operand tile, 8 x 16B chunks each
    const int t4 = tid >> 6, lg = tid & 63;
    const long aoff = (long)bz * sA + (long)m0 * K;
    const long boff = (long)bz * sB + (long)n0 * K;
    const __half* tsrc =
        (t4 == 0) ? (Ah + aoff) : (t4 == 1) ? (Al + aoff) :
        (t4 == 2) ? (Bh + boff) : (Bl + boff);
    // which operand tiles are actually consumed
    const bool do_fill =
        (NTERMS == 3) ? true :
        /* NTERMS==1 */ (t4 == 0 || t4 == 2);
    const int nT = K / KC;

    auto fill = [&](int kc) {
        if (do_fill) {
            u32 dbase = sb + (u32)(kc % STAGES) * STAGE_B + (u32)t4 * TILE_H;
            const __half* ksrc = tsrc + (long)kc * KC;
#pragma unroll
            for (int i = 0; i < 8; i++) {
                int idx = lg + i * 64;
                int row = idx >> 2, c = idx & 3;
                cp16(dbase + (u32)(row * ROWB + c * 16), ksrc + (long)row * K + c * 8);
            }
        }
        CP_COMMIT();
    };

#pragma unroll
    for (int s = 0; s < STAGES; s++) fill(s);

    float acc[4][4][4];
#pragma unroll
    for (int mi = 0; mi < 4; mi++)
#pragma unroll
        for (int nt = 0; nt < 4; nt++)
#pragma unroll
            for (int j = 0; j < 4; j++) acc[mi][nt][j] = 0.0f;

    // ldmatrix per-thread base offsets (bytes within an operand tile)
    const u32 aoffs = (u32)((wm * 64 + (lane & 15)) * ROWB + (lane >> 4) * 16);
    const u32 boffs = (u32)((wn * 32 + ((lane >> 4) << 3) + (lane & 7)) * ROWB
                            + ((lane >> 3) & 1) * 16);

    for (int t = 0; t < nT; t++) {
        int rem = nT - 1 - t; if (rem > STAGES - 1) rem = STAGES - 1;
        if (rem >= 2)      asm volatile("cp.async.wait_group 2;" ::: "memory");
        else if (rem == 1) asm volatile("cp.async.wait_group 1;" ::: "memory");
        else               asm volatile("cp.async.wait_group 0;" ::: "memory");
        __syncthreads();

        const u32 st = sb + (u32)(t % STAGES) * STAGE_B;
#pragma unroll
        for (int kk = 0; kk < 2; kk++) {
            u32 ahf[4][4], alf[4][4], bhf[2][4], blf[2][4];
#pragma unroll
            for (int mi = 0; mi < 4; mi++) {
                LDSM4(ahf[mi], st + aoffs + (u32)(mi * 16 * ROWB + kk * 32));
                if (NTERMS == 3)
                    LDSM4(alf[mi], st + TILE_H + aoffs + (u32)(mi * 16 * ROWB + kk * 32));
            }
#pragma unroll
            for (int p = 0; p < 2; p++) {
                LDSM4(bhf[p], st + 2 * TILE_H + boffs + (u32)(p * 16 * ROWB + kk * 32));
                if (NTERMS == 3)
                    LDSM4(blf[p], st + 3 * TILE_H + boffs + (u32)(p * 16 * ROWB + kk * 32));
            }
#pragma unroll
            for (int mi = 0; mi < 4; mi++)
#pragma unroll
                for (int nt = 0; nt < 4; nt++) {
                    u32 b0h = bhf[nt >> 1][(nt & 1) * 2], b1h = bhf[nt >> 1][(nt & 1) * 2 + 1];
                    MMA16816(acc[mi][nt], ahf[mi], b0h, b1h);
                    if (NTERMS == 3) {
                        u32 b0l = blf[nt >> 1][(nt & 1) * 2], b1l = blf[nt >> 1][(nt & 1) * 2 + 1];
                        MMA16816(acc[mi][nt], ahf[mi], b0l, b1l);
                        MMA16816(acc[mi][nt], alf[mi], b0h, b1h);
                    }
                }
        }
        __syncthreads();
        if (t + STAGES < nT) fill(t + STAGES);
    }

    // epilogue: fp32 acc frags straight to gmem
    float* Cb = C + (long)bz * sC;
    const int r = lane >> 2, c2 = (lane & 3) * 2;
#pragma unroll
    for (int mi = 0; mi < 4; mi++)
#pragma unroll
        for (int nt = 0; nt < 4; nt++) {
            long row = m0 + wm * 64 + mi * 16 + r;
            long col = n0 + wn * 32 + nt * 8 + c2;
            *(float2*)&Cb[row * Ncols + col] =
                make_float2(acc[mi][nt][0], acc[mi][nt][1]);
            *(float2*)&Cb[(row + 8) * Ncols + col] =
                make_float2(acc[mi][nt][2], acc[mi][nt][3]);
        }
}

// ---------------------------------------------------------------------------
// Launch
// ---------------------------------------------------------------------------
extern "C" void kernel_launch(void* const* d_in, const int* in_sizes, int n_in,
                              void* d_out, int out_size)
{
    const float* Q = (const float*)d_in[0];
    const float* V = (const float*)d_in[1];
    float* out  = (float*)d_out;
    float* ctx  = out;                                   // [B, LQ, DIM]
    float* attn = out + (size_t)BATCH * LQ * DIM;        // [B, LQ, LKV]

    void *qh, *ql, *vh, *vl, *vth, *ph;
    cudaGetSymbolAddress(&qh,  g_QH);  cudaGetSymbolAddress(&ql,  g_QL);
    cudaGetSymbolAddress(&vh,  g_VH);  cudaGetSymbolAddress(&vl,  g_VL);
    cudaGetSymbolAddress(&vth, g_VTH); cudaGetSymbolAddress(&ph,  g_PH);

    cudaFuncSetAttribute(gemm_nt_hmma<3>,
                         cudaFuncAttributeMaxDynamicSharedMemorySize, SMEM_GEMM);
    cudaFuncSetAttribute(gemm_nt_hmma<1>,
                         cudaFuncAttributeMaxDynamicSharedMemorySize, SMEM_GEMM);

    // 1) split Q
    {
        size_t n = (size_t)BATCH * LQ * DIM;
        cvt_split_kernel<<<(unsigned)(n / 4 / 256), 256>>>(
            Q, (__half*)qh, (__half*)ql);
    }
    // 2) split V + transposed (hi-only) V^T
    vtrans_kernel<<<dim3(DIM / 32, LKV / 32, BATCH), dim3(32, 8)>>>(
        V, (__half*)vh, (__half*)vl, (__half*)vth);

    // 3) S = Q @ V^T  (fp32 scores into attn region) — full 3-term accuracy
    gemm_nt_hmma<3><<<dim3(LKV / 128, LQ / 128, BATCH), 256, SMEM_GEMM>>>(
        (const __half*)qh, (const __half*)ql,
        (const __half*)vh, (const __half*)vl,
        attn, DIM, (long)LQ * DIM, (long)LKV * DIM, (long)LQ * LKV);

    // 4) softmax in place + P -> fp16
    softmax_split_kernel<<<BATCH * LQ, 256>>>(attn, (__half*)ph);

    // 5) context = P @ (V^T)^T — 1-term pure fp16 (P_lo and V_lo both
    //    contribute ~2^-12 relative; combined context err ~3-4e-4 < 1e-3)
    gemm_nt_hmma<1><<<dim3(DIM / 128, LQ / 128, BATCH), 256, SMEM_GEMM>>>(
        (const __half*)ph, (const __half*)ph,
        (const __half*)vth, (const __half*)vth,
        ctx, LKV, (long)LQ * LKV, (long)DIM * LKV, (long)LQ * DIM);
}